// round 1
// baseline (speedup 1.0000x reference)
#include <cuda_runtime.h>
#include <math.h>

// Problem dims
#define NB 2
#define NN 512
#define CSD 384
#define NH 12
#define NC 16
#define NP 8
#define NPV 8
#define NK 16
#define NG 64
#define HC (NH*NC)          // 192
#define HPV3 (NH*NPV*3)     // 288

// ---------------- scratch (device globals; no runtime allocation) -------------
__device__ __align__(16) float g_q   [NB*NN*HC];
__device__ __align__(16) float g_k   [NB*NN*HC];
__device__ __align__(16) float g_v   [NB*NN*HC];
__device__ __align__(16) float g_qpts[NB*NN*NP*3];
__device__ __align__(16) float g_vpts[NB*NN*NP*3];
__device__ __align__(16) float g_vg  [NB*NN*HPV3];
__device__ __align__(16) float g_logits[(size_t)NB*NH*NN*NN];
__device__ __align__(16) float g_o   [NB*NN*HC];
__device__ __align__(16) float g_opt [NB*NN*HPV3];

// ---------------- helpers ----------------
__device__ __forceinline__ float block_reduce_sum(float v, float* red) {
    int lane = threadIdx.x & 31, wid = threadIdx.x >> 5;
    #pragma unroll
    for (int o = 16; o > 0; o >>= 1) v += __shfl_down_sync(0xffffffffu, v, o);
    if (lane == 0) red[wid] = v;
    __syncthreads();
    int nw = (blockDim.x + 31) >> 5;
    float t = (threadIdx.x < nw) ? red[threadIdx.x] : 0.0f;
    if (wid == 0) {
        #pragma unroll
        for (int o = 16; o > 0; o >>= 1) t += __shfl_down_sync(0xffffffffu, t, o);
        if (lane == 0) red[0] = t;
    }
    __syncthreads();
    float r = red[0];
    __syncthreads();
    return r;
}

__device__ __forceinline__ float block_reduce_max(float v, float* red) {
    int lane = threadIdx.x & 31, wid = threadIdx.x >> 5;
    #pragma unroll
    for (int o = 16; o > 0; o >>= 1) v = fmaxf(v, __shfl_down_sync(0xffffffffu, v, o));
    if (lane == 0) red[wid] = v;
    __syncthreads();
    int nw = (blockDim.x + 31) >> 5;
    float t = (threadIdx.x < nw) ? red[threadIdx.x] : -1e30f;
    if (wid == 0) {
        #pragma unroll
        for (int o = 16; o > 0; o >>= 1) t = fmaxf(t, __shfl_down_sync(0xffffffffu, t, o));
        if (lane == 0) red[0] = t;
    }
    __syncthreads();
    float r = red[0];
    __syncthreads();
    return r;
}

// ================= K1: per-row projections =================
// block = one (b,n) row, 256 threads
__global__ void k1_project(const float* __restrict__ s,
                           const float* __restrict__ rot,
                           const float* __restrict__ trans,
                           const float* __restrict__ Wq,  const float* __restrict__ bq,
                           const float* __restrict__ Wkv, const float* __restrict__ bkv,
                           const float* __restrict__ ln_g,const float* __restrict__ ln_b,
                           const float* __restrict__ Wpq, const float* __restrict__ bpq,
                           const float* __restrict__ Wpv, const float* __restrict__ bpv,
                           const float* __restrict__ Wkvp,const float* __restrict__ bkvp)
{
    __shared__ float ssh[CSD];
    __shared__ float snsh[CSD];
    __shared__ float kvpsh[HPV3];
    __shared__ float red[32];

    int bn = blockIdx.x;
    int tid = threadIdx.x;
    const float* srow = s + (size_t)bn * CSD;
    for (int i = tid; i < CSD; i += blockDim.x) ssh[i] = srow[i];
    __syncthreads();

    // mean
    float ls = 0.f;
    for (int i = tid; i < CSD; i += blockDim.x) ls += ssh[i];
    float mean = block_reduce_sum(ls, red) * (1.0f / CSD);
    // var
    float lv = 0.f;
    for (int i = tid; i < CSD; i += blockDim.x) { float d = ssh[i] - mean; lv += d * d; }
    float var = block_reduce_sum(lv, red) * (1.0f / CSD);
    float inv = rsqrtf(var + 1e-5f);
    for (int i = tid; i < CSD; i += blockDim.x)
        snsh[i] = (ssh[i] - mean) * inv * ln_g[i] + ln_b[i];
    __syncthreads();

    // fused GEMVs: 912 output columns
    for (int col = tid; col < 912; col += blockDim.x) {
        if (col < HC) {                     // q
            float acc = bq[col];
            #pragma unroll 4
            for (int cs = 0; cs < CSD; cs++) acc += ssh[cs] * Wq[(size_t)cs * HC + col];
            g_q[(size_t)bn * HC + col] = acc;
        } else if (col < HC + 2*HC) {       // kv (384 cols)
            int j2 = col - HC;
            float acc = bkv[j2];
            #pragma unroll 4
            for (int cs = 0; cs < CSD; cs++) acc += ssh[cs] * Wkv[(size_t)cs * (2*HC) + j2];
            int h = j2 >> 5, r = j2 & 31;
            if (r < NC) g_k[(size_t)bn * HC + h * NC + r] = acc;
            else        g_v[(size_t)bn * HC + h * NC + (r - NC)] = acc;
        } else if (col < 600) {             // q_pts (24)
            int c2 = col - 576;
            float acc = bpq[c2];
            #pragma unroll 4
            for (int cs = 0; cs < CSD; cs++) acc += snsh[cs] * Wpq[(size_t)cs * (NP*3) + c2];
            g_qpts[(size_t)bn * (NP*3) + c2] = acc;
        } else if (col < 624) {             // v_pts (24)
            int c2 = col - 600;
            float acc = bpv[c2];
            #pragma unroll 4
            for (int cs = 0; cs < CSD; cs++) acc += snsh[cs] * Wpv[(size_t)cs * (NP*3) + c2];
            g_vpts[(size_t)bn * (NP*3) + c2] = acc;
        } else {                            // kv_pts (288)
            int c2 = col - 624;
            float acc = bkvp[c2];
            #pragma unroll 4
            for (int cs = 0; cs < CSD; cs++) acc += ssh[cs] * Wkvp[(size_t)cs * HPV3 + c2];
            kvpsh[c2] = acc;
        }
    }
    __syncthreads();

    // vg = rot @ kv_pts + trans*0.1
    const float* rp = rot + (size_t)bn * 9;
    const float* tp = trans + (size_t)bn * 3;
    for (int t = tid; t < HPV3; t += blockDim.x) {
        int kidx = t / 3, x = t % 3;
        float vv = tp[x] * 0.1f;
        #pragma unroll
        for (int y = 0; y < 3; y++) vv += rp[x * 3 + y] * kvpsh[kidx * 3 + y];
        g_vg[(size_t)bn * HPV3 + t] = vv;
    }
}

// ================= K2: pair stage =================
// dynamic shared layout (floats)
#define OFF_WG    0
#define OFF_W1    8192
#define OFF_W2    12288
#define OFF_WVL   13056
#define OFF_MEAN  13184
#define OFF_ISTD  13200
#define OFF_BG    13216
#define OFF_B1    13280
#define OFF_B2    13344
#define OFF_HW    13356
#define OFF_ROTI  13368
#define OFF_TI    13377
#define OFF_QPTS  13380
#define OFF_QVL   13404
#define OFF_MASKI 13428
#define OFF_QI    13432
#define WARP_BASE 13624
#define SMEM2_FLOATS (WARP_BASE + 8*288)     // 15928
#define SMEM2_BYTES  (SMEM2_FLOATS * 4)

__global__ void k2_pair(const float* __restrict__ rot,
                        const float* __restrict__ trans,
                        const float* __restrict__ mask,
                        const float* __restrict__ head_weights,
                        const float* __restrict__ Wvl,
                        const float* __restrict__ gbf_means,
                        const float* __restrict__ gbf_stds,
                        const float* __restrict__ Wg, const float* __restrict__ bg,
                        const float* __restrict__ W1, const float* __restrict__ b1,
                        const float* __restrict__ W2, const float* __restrict__ b2,
                        float* __restrict__ g_out)
{
    extern __shared__ float sh[];
    int bi = blockIdx.x;
    int b = bi >> 9, i = bi & 511;
    int tid = threadIdx.x;

    for (int t = tid; t < 8192; t += blockDim.x) sh[OFF_WG + t] = Wg[t];
    for (int t = tid; t < 4096; t += blockDim.x) sh[OFF_W1 + t] = W1[t];
    for (int t = tid; t < 768;  t += blockDim.x) sh[OFF_W2 + t] = W2[t];
    if (tid < 128) sh[OFF_WVL + tid] = Wvl[tid];
    if (tid < NK) {
        sh[OFF_MEAN + tid] = gbf_means[tid];
        sh[OFF_ISTD + tid] = 1.0f / gbf_stds[tid];
    }
    if (tid < NG) { sh[OFF_BG + tid] = bg[tid]; sh[OFF_B1 + tid] = b1[tid]; }
    if (tid < NH) {
        sh[OFF_B2 + tid] = b2[tid];
        float x = head_weights[tid];
        float sp = logf(1.0f + expf(x));
        sh[OFF_HW + tid] = sp * (-0.11785113f);   // softplus * sqrt(1/18) * -0.5
    }
    if (tid < 9) sh[OFF_ROTI + tid] = rot[(size_t)bi * 9 + tid];
    if (tid < 3) sh[OFF_TI + tid] = trans[(size_t)bi * 3 + tid];
    if (tid < 24) sh[OFF_QPTS + tid] = g_qpts[(size_t)bi * 24 + tid];
    if (tid == 0) sh[OFF_MASKI] = mask[bi];
    if (tid < HC) sh[OFF_QI + tid] = g_q[(size_t)bi * HC + tid];
    __syncthreads();

    if (tid < 24) {  // q-contribution of Wvl (j-independent)
        int o = tid / 3, x = tid % 3;
        float acc = 0.f;
        #pragma unroll
        for (int p = 0; p < NP; p++)
            acc += sh[OFF_WVL + o * 16 + 8 + p] * sh[OFF_QPTS + p * 3 + x];
        sh[OFF_QVL + tid] = acc;
    }
    __syncthreads();

    int wid = tid >> 5, lane = tid & 31;
    float* wb = sh + WARP_BASE + wid * 288;  // [vloc 24][vlen 8][gauss 128][g 64][h1 64]
    float ti0 = sh[OFF_TI + 0], ti1 = sh[OFF_TI + 1], ti2 = sh[OFF_TI + 2];
    float mi = sh[OFF_MASKI];

    for (int j = wid; j < NN; j += 8) {
        // ---- A: v_loc (lanes 0..23, each one (p,x)) ----
        if (lane < 24) {
            int p = lane / 3, x = lane % 3;
            const float* rj = rot + ((size_t)b * NN + j) * 9;
            const float* tj = trans + ((size_t)b * NN + j) * 3;
            float R0 = 0.f, R1 = 0.f, R2 = 0.f, tr = 0.f;
            #pragma unroll
            for (int w = 0; w < 3; w++) {
                float a = sh[OFF_ROTI + w * 3 + x];
                R0 += a * rj[w * 3 + 0];
                R1 += a * rj[w * 3 + 1];
                R2 += a * rj[w * 3 + 2];
                float tw = (w == 0) ? ti0 : (w == 1 ? ti1 : ti2);
                tr += a * (tj[w] - tw);
            }
            const float* vp = g_vpts + ((size_t)b * NN + j) * 24 + p * 3;
            wb[p * 3 + x] = R0 * vp[0] + R1 * vp[1] + R2 * vp[2] + tr;
        }
        __syncwarp();
        // ---- B: vec + vlen (lanes 0..7) ----
        if (lane < 8) {
            int o = lane;
            float vx = sh[OFF_QVL + o*3+0] + wb[o*3+0];
            float vy = sh[OFF_QVL + o*3+1] + wb[o*3+1];
            float vz = sh[OFF_QVL + o*3+2] + wb[o*3+2];
            #pragma unroll
            for (int p = 0; p < NP; p++) {
                float w_ = sh[OFF_WVL + o * 16 + p];
                vx += w_ * wb[p*3+0];
                vy += w_ * wb[p*3+1];
                vz += w_ * wb[p*3+2];
            }
            wb[24 + o] = sqrtf(vx*vx + vy*vy + vz*vz + 1e-8f);
        }
        __syncwarp();
        // ---- C: gauss (4 per lane) ----
        {
            int base = lane * 4;
            #pragma unroll
            for (int t = 0; t < 4; t++) {
                int idx = base + t;
                int p = idx >> 4, kk = idx & 15;
                float d = (wb[24 + p] - sh[OFF_MEAN + kk]) * sh[OFF_ISTD + kk];
                wb[32 + idx] = __expf(-0.5f * d * d);
            }
        }
        __syncwarp();
        // ---- D: g = gauss @ Wg + bg (2 outputs/lane), write to output ----
        {
            float a0 = sh[OFF_BG + lane], a1 = sh[OFF_BG + lane + 32];
            #pragma unroll 8
            for (int m = 0; m < 128; m++) {
                float ga = wb[32 + m];
                a0 += ga * sh[OFF_WG + m * 64 + lane];
                a1 += ga * sh[OFF_WG + m * 64 + lane + 32];
            }
            wb[160 + lane]      = a0;
            wb[160 + lane + 32] = a1;
            size_t go = (((size_t)bi) * NN + j) * NG;
            g_out[go + lane]      = a0;
            g_out[go + lane + 32] = a1;
        }
        __syncwarp();
        // ---- E: h1 = relu(g @ W1 + b1) ----
        {
            float a0 = sh[OFF_B1 + lane], a1 = sh[OFF_B1 + lane + 32];
            #pragma unroll 8
            for (int m = 0; m < 64; m++) {
                float gm = wb[160 + m];
                a0 += gm * sh[OFF_W1 + m * 64 + lane];
                a1 += gm * sh[OFF_W1 + m * 64 + lane + 32];
            }
            wb[224 + lane]      = fmaxf(a0, 0.f);
            wb[224 + lane + 32] = fmaxf(a1, 0.f);
        }
        __syncwarp();
        // ---- F: vfn + qk + dist -> logits (lanes 0..11) ----
        if (lane < NH) {
            float acc = sh[OFF_B2 + lane];
            #pragma unroll 8
            for (int m = 0; m < 64; m++)
                acc += wb[224 + m] * sh[OFF_W2 + m * NH + lane];
            const float* kp = g_k + ((size_t)b * NN + j) * HC + lane * NC;
            const float* qp = sh + OFF_QI + lane * NC;
            float qk = 0.f;
            #pragma unroll
            for (int c = 0; c < NC; c++) qk += qp[c] * kp[c];
            const float* tj = trans + ((size_t)b * NN + j) * 3;
            float d0 = (tj[0] - ti0) * 0.1f;
            float d1 = (tj[1] - ti1) * 0.1f;
            float d2 = (tj[2] - ti2) * 0.1f;
            float pd = d0*d0 + d1*d1 + d2*d2;
            float mj = mask[(size_t)b * NN + j];
            float logit = qk * 0.125f + acc * 0.5f + pd * sh[OFF_HW + lane]
                        + 100000.0f * (mi * mj - 1.0f);
            g_logits[((((size_t)b * NH + lane) * NN) + i) * NN + j] = logit;
        }
        __syncwarp();
    }
}

// ================= K3: softmax over last dim =================
__global__ void k3_softmax()
{
    __shared__ float red[32];
    size_t row = blockIdx.x;
    float* p = g_logits + row * NN;
    int tid = threadIdx.x;
    float v0 = p[tid], v1 = p[tid + 256];
    float mx = block_reduce_max(fmaxf(v0, v1), red);
    float e0 = __expf(v0 - mx), e1 = __expf(v1 - mx);
    float sum = block_reduce_sum(e0 + e1, red);
    float inv = 1.0f / sum;
    p[tid] = e0 * inv;
    p[tid + 256] = e1 * inv;
}

// ================= K4: attention-weighted sums (o and o_pt) =================
__global__ void k4_attn()
{
    __shared__ float pr[NH * NN];   // 24KB
    int bi = blockIdx.x;
    int b = bi >> 9, i = bi & 511;
    int tid = threadIdx.x;
    for (int t = tid; t < NH * NN; t += blockDim.x) {
        int h = t >> 9, j = t & 511;
        pr[t] = g_logits[((((size_t)b * NH + h) * NN) + i) * NN + j];
    }
    __syncthreads();

    for (int idx = tid; idx < HC + HPV3; idx += blockDim.x) {
        if (idx < HC) {
            int h = idx >> 4;
            const float* vp = g_v + (size_t)b * NN * HC + idx;
            const float* ph = pr + h * NN;
            float acc = 0.f;
            #pragma unroll 4
            for (int j = 0; j < NN; j++) acc += ph[j] * vp[(size_t)j * HC];
            g_o[(size_t)bi * HC + idx] = acc;
        } else {
            int i2 = idx - HC;
            int h = i2 / 24;
            const float* vp = g_vg + (size_t)b * NN * HPV3 + i2;
            const float* ph = pr + h * NN;
            float acc = 0.f;
            #pragma unroll 4
            for (int j = 0; j < NN; j++) acc += ph[j] * vp[(size_t)j * HPV3];
            g_opt[(size_t)bi * HPV3 + i2] = acc;
        }
    }
}

// ================= K5: final features + output GEMV =================
__global__ void k5_out(const float* __restrict__ rot,
                       const float* __restrict__ trans,
                       const float* __restrict__ Wout,
                       const float* __restrict__ bout,
                       float* __restrict__ sout)
{
    __shared__ float feats[576];
    int bi = blockIdx.x;
    int tid = threadIdx.x;
    const float* op = g_o + (size_t)bi * HC;
    for (int t = tid; t < HC; t += blockDim.x) feats[t] = op[t];
    const float* rp = rot + (size_t)bi * 9;
    const float* tp = trans + (size_t)bi * 3;
    if (tid < 96) {
        int kidx = tid;
        float oy0 = g_opt[(size_t)bi * HPV3 + kidx*3+0] - tp[0] * 0.1f;
        float oy1 = g_opt[(size_t)bi * HPV3 + kidx*3+1] - tp[1] * 0.1f;
        float oy2 = g_opt[(size_t)bi * HPV3 + kidx*3+2] - tp[2] * 0.1f;
        float l0 = rp[0]*oy0 + rp[3]*oy1 + rp[6]*oy2;
        float l1 = rp[1]*oy0 + rp[4]*oy1 + rp[7]*oy2;
        float l2 = rp[2]*oy0 + rp[5]*oy1 + rp[8]*oy2;
        feats[192 + kidx] = l0;
        feats[288 + kidx] = l1;
        feats[384 + kidx] = l2;
        feats[480 + kidx] = sqrtf(l0*l0 + l1*l1 + l2*l2 + 1e-8f);
    }
    __syncthreads();
    int cs = tid;  // blockDim = 384
    float acc = bout[cs];
    #pragma unroll 4
    for (int f = 0; f < 576; f++) acc += feats[f] * Wout[(size_t)f * CSD + cs];
    sout[(size_t)bi * CSD + cs] = acc;
}

// ================= launch =================
extern "C" void kernel_launch(void* const* d_in, const int* in_sizes, int n_in,
                              void* d_out, int out_size)
{
    const float* s        = (const float*)d_in[0];
    const float* rot      = (const float*)d_in[1];
    const float* trans    = (const float*)d_in[2];
    const float* mask     = (const float*)d_in[3];
    const float* Wq       = (const float*)d_in[4];
    const float* bq       = (const float*)d_in[5];
    const float* Wkv      = (const float*)d_in[6];
    const float* bkv      = (const float*)d_in[7];
    const float* head_w   = (const float*)d_in[8];
    const float* ln_g     = (const float*)d_in[9];
    const float* ln_b     = (const float*)d_in[10];
    const float* Wpq      = (const float*)d_in[11];
    const float* bpq      = (const float*)d_in[12];
    const float* Wpv      = (const float*)d_in[13];
    const float* bpv      = (const float*)d_in[14];
    const float* Wvl      = (const float*)d_in[15];
    const float* gbf_mean = (const float*)d_in[16];
    const float* gbf_std  = (const float*)d_in[17];
    const float* Wg       = (const float*)d_in[18];
    const float* bg       = (const float*)d_in[19];
    const float* W1       = (const float*)d_in[20];
    const float* b1       = (const float*)d_in[21];
    const float* W2       = (const float*)d_in[22];
    const float* b2       = (const float*)d_in[23];
    const float* Wkvp     = (const float*)d_in[24];
    const float* bkvp     = (const float*)d_in[25];
    const float* Wout     = (const float*)d_in[26];
    const float* bout     = (const float*)d_in[27];

    float* out = (float*)d_out;
    float* sout_part = out;                              // (B,N,CS)
    float* g_part = out + (size_t)NB * NN * CSD;         // (B,N,N,G)

    cudaFuncSetAttribute((const void*)k2_pair,
                         cudaFuncAttributeMaxDynamicSharedMemorySize, SMEM2_BYTES);

    k1_project<<<NB * NN, 256>>>(s, rot, trans, Wq, bq, Wkv, bkv,
                                 ln_g, ln_b, Wpq, bpq, Wpv, bpv, Wkvp, bkvp);
    k2_pair<<<NB * NN, 256, SMEM2_BYTES>>>(rot, trans, mask, head_w, Wvl,
                                           gbf_mean, gbf_std, Wg, bg, W1, b1,
                                           W2, b2, g_part);
    k3_softmax<<<NB * NH * NN, 256>>>();
    k4_attn<<<NB * NN, 256>>>();
    k5_out<<<NB * NN, 384>>>(rot, trans, Wout, bout, sout_part);
}

// round 2
// speedup vs baseline: 1.8082x; 1.8082x over previous
#include <cuda_runtime.h>
#include <math.h>

// Problem dims
#define NB 2
#define NN 512
#define CSD 384
#define NH 12
#define NC 16
#define NP 8
#define NPV 8
#define NK 16
#define NG 64
#define HC (NH*NC)          // 192
#define HPV3 (NH*NPV*3)     // 288

// ---------------- scratch (device globals) -------------
__device__ __align__(16) float g_q   [NB*NN*HC];
__device__ __align__(16) float g_k   [NB*NN*HC];
__device__ __align__(16) float g_v   [NB*NN*HC];
__device__ __align__(16) float g_qpts[NB*NN*NP*3];
__device__ __align__(16) float g_vpts[NB*NN*NP*3];
__device__ __align__(16) float g_vg  [NB*NN*HPV3];
__device__ __align__(16) float g_logits[(size_t)NB*NH*NN*NN];
__device__ __align__(16) float g_o   [NB*NN*HC];
__device__ __align__(16) float g_opt [NB*NN*HPV3];

// ================= K1: per-row projections, 8 rows per block =================
#define K1R 8
__global__ void k1_project(const float* __restrict__ s,
                           const float* __restrict__ rot,
                           const float* __restrict__ trans,
                           const float* __restrict__ Wq,  const float* __restrict__ bq,
                           const float* __restrict__ Wkv, const float* __restrict__ bkv,
                           const float* __restrict__ ln_g,const float* __restrict__ ln_b,
                           const float* __restrict__ Wpq, const float* __restrict__ bpq,
                           const float* __restrict__ Wpv, const float* __restrict__ bpv,
                           const float* __restrict__ Wkvp,const float* __restrict__ bkvp)
{
    __shared__ float ssh [K1R*CSD];
    __shared__ float snsh[K1R*CSD];
    __shared__ float kvpsh[K1R*HPV3];

    int bn0 = blockIdx.x * K1R;
    int tid = threadIdx.x;
    int wid = tid >> 5, lane = tid & 31;

    for (int idx = tid; idx < K1R*CSD; idx += blockDim.x)
        ssh[idx] = s[(size_t)bn0 * CSD + idx];
    __syncthreads();

    // each warp does layernorm for its row
    {
        int r = wid;
        const float* row = ssh + r * CSD;
        float lsum = 0.f;
        for (int i = lane; i < CSD; i += 32) lsum += row[i];
        #pragma unroll
        for (int o = 16; o > 0; o >>= 1) lsum += __shfl_xor_sync(0xffffffffu, lsum, o);
        float mean = lsum * (1.0f / CSD);
        float lvar = 0.f;
        for (int i = lane; i < CSD; i += 32) { float d = row[i] - mean; lvar += d * d; }
        #pragma unroll
        for (int o = 16; o > 0; o >>= 1) lvar += __shfl_xor_sync(0xffffffffu, lvar, o);
        float inv = rsqrtf(lvar * (1.0f / CSD) + 1e-5f);
        for (int i = lane; i < CSD; i += 32)
            snsh[r * CSD + i] = (row[i] - mean) * inv * ln_g[i] + ln_b[i];
    }
    __syncthreads();

    // fused GEMVs: 912 output columns, 8 rows per column-thread
    for (int col = tid; col < 912; col += blockDim.x) {
        float acc[K1R];
        if (col < HC) {
            #pragma unroll
            for (int r = 0; r < K1R; r++) acc[r] = bq[col];
            for (int cs = 0; cs < CSD; cs++) {
                float w = Wq[(size_t)cs * HC + col];
                #pragma unroll
                for (int r = 0; r < K1R; r++) acc[r] += ssh[r*CSD+cs] * w;
            }
            #pragma unroll
            for (int r = 0; r < K1R; r++) g_q[(size_t)(bn0+r) * HC + col] = acc[r];
        } else if (col < 3*HC) {
            int j2 = col - HC;
            #pragma unroll
            for (int r = 0; r < K1R; r++) acc[r] = bkv[j2];
            for (int cs = 0; cs < CSD; cs++) {
                float w = Wkv[(size_t)cs * (2*HC) + j2];
                #pragma unroll
                for (int r = 0; r < K1R; r++) acc[r] += ssh[r*CSD+cs] * w;
            }
            int h = j2 >> 5, rr = j2 & 31;
            #pragma unroll
            for (int r = 0; r < K1R; r++) {
                if (rr < NC) g_k[(size_t)(bn0+r) * HC + h * NC + rr] = acc[r];
                else         g_v[(size_t)(bn0+r) * HC + h * NC + (rr - NC)] = acc[r];
            }
        } else if (col < 600) {
            int c2 = col - 576;
            #pragma unroll
            for (int r = 0; r < K1R; r++) acc[r] = bpq[c2];
            for (int cs = 0; cs < CSD; cs++) {
                float w = Wpq[(size_t)cs * (NP*3) + c2];
                #pragma unroll
                for (int r = 0; r < K1R; r++) acc[r] += snsh[r*CSD+cs] * w;
            }
            #pragma unroll
            for (int r = 0; r < K1R; r++) g_qpts[(size_t)(bn0+r) * (NP*3) + c2] = acc[r];
        } else if (col < 624) {
            int c2 = col - 600;
            #pragma unroll
            for (int r = 0; r < K1R; r++) acc[r] = bpv[c2];
            for (int cs = 0; cs < CSD; cs++) {
                float w = Wpv[(size_t)cs * (NP*3) + c2];
                #pragma unroll
                for (int r = 0; r < K1R; r++) acc[r] += snsh[r*CSD+cs] * w;
            }
            #pragma unroll
            for (int r = 0; r < K1R; r++) g_vpts[(size_t)(bn0+r) * (NP*3) + c2] = acc[r];
        } else {
            int c2 = col - 624;
            #pragma unroll
            for (int r = 0; r < K1R; r++) acc[r] = bkvp[c2];
            for (int cs = 0; cs < CSD; cs++) {
                float w = Wkvp[(size_t)cs * HPV3 + c2];
                #pragma unroll
                for (int r = 0; r < K1R; r++) acc[r] += ssh[r*CSD+cs] * w;
            }
            #pragma unroll
            for (int r = 0; r < K1R; r++) kvpsh[r*HPV3 + c2] = acc[r];
        }
    }
    __syncthreads();

    // vg = rot @ kv_pts + trans*0.1
    for (int t = tid; t < K1R*HPV3; t += blockDim.x) {
        int r = t / HPV3, e = t - r*HPV3;
        int kidx = e / 3, x = e % 3;
        int bn = bn0 + r;
        const float* rp = rot + (size_t)bn * 9;
        const float* tp = trans + (size_t)bn * 3;
        float vv = tp[x] * 0.1f;
        #pragma unroll
        for (int y = 0; y < 3; y++) vv += rp[x * 3 + y] * kvpsh[r*HPV3 + kidx * 3 + y];
        g_vg[(size_t)bn * HPV3 + e] = vv;
    }
}

// ================= K2: pair stage (j-tiled GEMM) =================
// shared layout (floats)
#define OFF_WG    0          // [128][64]
#define OFF_W1    8192       // [64][64]
#define OFF_W2    12288      // [64][12]
#define OFF_WVL   13056      // 128
#define OFF_MEAN  13184
#define OFF_ISTD  13200
#define OFF_BG    13216
#define OFF_B1    13280
#define OFF_B2    13344
#define OFF_HW    13356
#define OFF_ROTI  13368
#define OFF_TI    13377
#define OFF_QPTS  13380
#define OFF_QVL   13404
#define OFF_MASKI 13428
#define OFF_QI    13432      // 192, end 13624
#define OFF_VLOC  13632      // [64][25] -> 1600, end 15232
#define OFF_VLEN  15232      // [64][8]  -> 512,  end 15744
#define OFF_GAU   15744      // [64][132]-> 8448, end 24192 (reused for h1)
#define OFF_GB    24192      // [64][68] -> 4352, end 28544
#define SMEM2_FLOATS 28544
#define SMEM2_BYTES  (SMEM2_FLOATS * 4)
#define JT 64

__global__ void k2_pair(const float* __restrict__ rot,
                        const float* __restrict__ trans,
                        const float* __restrict__ mask,
                        const float* __restrict__ head_weights,
                        const float* __restrict__ Wvl,
                        const float* __restrict__ gbf_means,
                        const float* __restrict__ gbf_stds,
                        const float* __restrict__ Wg, const float* __restrict__ bg,
                        const float* __restrict__ W1, const float* __restrict__ b1,
                        const float* __restrict__ W2, const float* __restrict__ b2,
                        float* __restrict__ g_out)
{
    extern __shared__ float sh[];
    int bi = blockIdx.x;
    int b = bi >> 9, i = bi & 511;
    int tid = threadIdx.x;

    for (int t = tid; t < 8192; t += 256) sh[OFF_WG + t] = Wg[t];
    for (int t = tid; t < 4096; t += 256) sh[OFF_W1 + t] = W1[t];
    for (int t = tid; t < 768;  t += 256) sh[OFF_W2 + t] = W2[t];
    if (tid < 128) sh[OFF_WVL + tid] = Wvl[tid];
    if (tid < NK) {
        sh[OFF_MEAN + tid] = gbf_means[tid];
        sh[OFF_ISTD + tid] = 1.0f / gbf_stds[tid];
    }
    if (tid < NG) { sh[OFF_BG + tid] = bg[tid]; sh[OFF_B1 + tid] = b1[tid]; }
    if (tid < NH) {
        sh[OFF_B2 + tid] = b2[tid];
        float x = head_weights[tid];
        float sp = logf(1.0f + expf(x));
        sh[OFF_HW + tid] = sp * (-0.11785113f);   // softplus * sqrt(1/18) * -0.5
    }
    if (tid < 9) sh[OFF_ROTI + tid] = rot[(size_t)bi * 9 + tid];
    if (tid < 3) sh[OFF_TI + tid] = trans[(size_t)bi * 3 + tid];
    if (tid < 24) sh[OFF_QPTS + tid] = g_qpts[(size_t)bi * 24 + tid];
    if (tid == 0) sh[OFF_MASKI] = mask[bi];
    if (tid < HC) sh[OFF_QI + tid] = g_q[(size_t)bi * HC + tid];
    __syncthreads();

    if (tid < 24) {  // q-contribution of Wvl (j-independent)
        int o = tid / 3, x = tid % 3;
        float acc = 0.f;
        #pragma unroll
        for (int p = 0; p < NP; p++)
            acc += sh[OFF_WVL + o * 16 + 8 + p] * sh[OFF_QPTS + p * 3 + x];
        sh[OFF_QVL + tid] = acc;
    }
    __syncthreads();

    float ti0 = sh[OFF_TI + 0], ti1 = sh[OFF_TI + 1], ti2 = sh[OFF_TI + 2];
    float mi = sh[OFF_MASKI];
    int ty = tid >> 4, tx = tid & 15;    // for the GEMM stages

    const float4* WG4 = (const float4*)(sh + OFF_WG);
    const float4* W14 = (const float4*)(sh + OFF_W1);

    for (int j0 = 0; j0 < NN; j0 += JT) {
        // ---- A: v_loc for the tile: thread = (jj, quarter) ----
        {
            int jj = tid >> 2, qq = tid & 3;
            int j = j0 + jj;
            const float* rj = rot + ((size_t)b * NN + j) * 9;
            const float* tj = trans + ((size_t)b * NN + j) * 3;
            float R[3][3], tr[3];
            #pragma unroll
            for (int x = 0; x < 3; x++) {
                float a0 = sh[OFF_ROTI + 0*3 + x];
                float a1 = sh[OFF_ROTI + 1*3 + x];
                float a2 = sh[OFF_ROTI + 2*3 + x];
                #pragma unroll
                for (int z = 0; z < 3; z++)
                    R[x][z] = a0 * rj[0*3+z] + a1 * rj[1*3+z] + a2 * rj[2*3+z];
                tr[x] = a0 * (tj[0] - ti0) + a1 * (tj[1] - ti1) + a2 * (tj[2] - ti2);
            }
            #pragma unroll
            for (int pp = 0; pp < 2; pp++) {
                int p = qq * 2 + pp;
                const float* vp = g_vpts + ((size_t)b * NN + j) * 24 + p * 3;
                float v0 = vp[0], v1 = vp[1], v2 = vp[2];
                #pragma unroll
                for (int x = 0; x < 3; x++)
                    sh[OFF_VLOC + jj*25 + p*3 + x] = R[x][0]*v0 + R[x][1]*v1 + R[x][2]*v2 + tr[x];
            }
        }
        __syncthreads();
        // ---- B: vec + vlen: thread = (jj, quarter->2 o's) ----
        {
            int jj = tid >> 2, qq = tid & 3;
            const float* vl = sh + OFF_VLOC + jj*25;
            #pragma unroll
            for (int oo = 0; oo < 2; oo++) {
                int o = qq * 2 + oo;
                float vx = sh[OFF_QVL + o*3+0] + vl[o*3+0];
                float vy = sh[OFF_QVL + o*3+1] + vl[o*3+1];
                float vz = sh[OFF_QVL + o*3+2] + vl[o*3+2];
                #pragma unroll
                for (int p = 0; p < NP; p++) {
                    float w_ = sh[OFF_WVL + o * 16 + p];
                    vx += w_ * vl[p*3+0];
                    vy += w_ * vl[p*3+1];
                    vz += w_ * vl[p*3+2];
                }
                sh[OFF_VLEN + jj*8 + o] = sqrtf(vx*vx + vy*vy + vz*vz + 1e-8f);
            }
        }
        __syncthreads();
        // ---- C: gauss [64][128] ----
        #pragma unroll
        for (int it = 0; it < 32; it++) {
            int flat = tid + 256 * it;
            int jj = flat >> 7, m = flat & 127;
            int p = m >> 4, kk = m & 15;
            float d = (sh[OFF_VLEN + jj*8 + p] - sh[OFF_MEAN + kk]) * sh[OFF_ISTD + kk];
            sh[OFF_GAU + jj*132 + m] = __expf(-0.5f * d * d);
        }
        __syncthreads();
        // ---- D: g[64][64] = gauss @ Wg + bg (4x4 register tile) ----
        {
            float acc[4][4];
            #pragma unroll
            for (int r = 0; r < 4; r++)
                #pragma unroll
                for (int c = 0; c < 4; c++) acc[r][c] = sh[OFF_BG + tx*4 + c];
            #pragma unroll 4
            for (int m = 0; m < 128; m++) {
                float4 wv = WG4[m * 16 + tx];
                float ga0 = sh[OFF_GAU + (4*ty+0)*132 + m];
                float ga1 = sh[OFF_GAU + (4*ty+1)*132 + m];
                float ga2 = sh[OFF_GAU + (4*ty+2)*132 + m];
                float ga3 = sh[OFF_GAU + (4*ty+3)*132 + m];
                acc[0][0] += ga0*wv.x; acc[0][1] += ga0*wv.y; acc[0][2] += ga0*wv.z; acc[0][3] += ga0*wv.w;
                acc[1][0] += ga1*wv.x; acc[1][1] += ga1*wv.y; acc[1][2] += ga1*wv.z; acc[1][3] += ga1*wv.w;
                acc[2][0] += ga2*wv.x; acc[2][1] += ga2*wv.y; acc[2][2] += ga2*wv.z; acc[2][3] += ga2*wv.w;
                acc[3][0] += ga3*wv.x; acc[3][1] += ga3*wv.y; acc[3][2] += ga3*wv.z; acc[3][3] += ga3*wv.w;
            }
            #pragma unroll
            for (int r = 0; r < 4; r++) {
                int jj = 4*ty + r;
                float4 v4 = make_float4(acc[r][0], acc[r][1], acc[r][2], acc[r][3]);
                *(float4*)(sh + OFF_GB + jj*68 + tx*4) = v4;
                *(float4*)(g_out + ((size_t)bi * NN + j0 + jj) * NG + tx*4) = v4;
            }
        }
        __syncthreads();
        // ---- E: h1[64][64] = relu(g @ W1 + b1), written into GAU buffer ----
        {
            float acc[4][4];
            #pragma unroll
            for (int r = 0; r < 4; r++)
                #pragma unroll
                for (int c = 0; c < 4; c++) acc[r][c] = sh[OFF_B1 + tx*4 + c];
            #pragma unroll 4
            for (int m = 0; m < 64; m++) {
                float4 wv = W14[m * 16 + tx];
                float ga0 = sh[OFF_GB + (4*ty+0)*68 + m];
                float ga1 = sh[OFF_GB + (4*ty+1)*68 + m];
                float ga2 = sh[OFF_GB + (4*ty+2)*68 + m];
                float ga3 = sh[OFF_GB + (4*ty+3)*68 + m];
                acc[0][0] += ga0*wv.x; acc[0][1] += ga0*wv.y; acc[0][2] += ga0*wv.z; acc[0][3] += ga0*wv.w;
                acc[1][0] += ga1*wv.x; acc[1][1] += ga1*wv.y; acc[1][2] += ga1*wv.z; acc[1][3] += ga1*wv.w;
                acc[2][0] += ga2*wv.x; acc[2][1] += ga2*wv.y; acc[2][2] += ga2*wv.z; acc[2][3] += ga2*wv.w;
                acc[3][0] += ga3*wv.x; acc[3][1] += ga3*wv.y; acc[3][2] += ga3*wv.z; acc[3][3] += ga3*wv.w;
            }
            __syncthreads();   // GAU (gauss) fully consumed in D; safe to overwrite
            #pragma unroll
            for (int r = 0; r < 4; r++) {
                int jj = 4*ty + r;
                float4 v4 = make_float4(fmaxf(acc[r][0],0.f), fmaxf(acc[r][1],0.f),
                                        fmaxf(acc[r][2],0.f), fmaxf(acc[r][3],0.f));
                *(float4*)(sh + OFF_GAU + jj*132 + tx*4) = v4;
            }
        }
        __syncthreads();
        // ---- F: vfn + qk + dist -> logits ----
        for (int idx = tid; idx < JT * NH; idx += 256) {
            int jj = idx / NH, h = idx - jj * NH;
            int j = j0 + jj;
            float acc = sh[OFF_B2 + h];
            const float* h1 = sh + OFF_GAU + jj*132;
            #pragma unroll 8
            for (int m = 0; m < 64; m++)
                acc += h1[m] * sh[OFF_W2 + m * NH + h];
            const float4* kp = (const float4*)(g_k + ((size_t)b * NN + j) * HC + h * NC);
            const float4* qp = (const float4*)(sh + OFF_QI + h * NC);
            float qk = 0.f;
            #pragma unroll
            for (int c = 0; c < 4; c++) {
                float4 kk4 = kp[c], qq4 = qp[c];
                qk += qq4.x*kk4.x + qq4.y*kk4.y + qq4.z*kk4.z + qq4.w*kk4.w;
            }
            const float* tj = trans + ((size_t)b * NN + j) * 3;
            float d0 = (tj[0] - ti0) * 0.1f;
            float d1 = (tj[1] - ti1) * 0.1f;
            float d2 = (tj[2] - ti2) * 0.1f;
            float pd = d0*d0 + d1*d1 + d2*d2;
            float mj = mask[(size_t)b * NN + j];
            float logit = qk * 0.125f + acc * 0.5f + pd * sh[OFF_HW + h]
                        + 100000.0f * (mi * mj - 1.0f);
            g_logits[((((size_t)b * NH + h) * NN) + i) * NN + j] = logit;
        }
        __syncthreads();
    }
}

// ================= K3: softmax over last dim =================
__global__ void k3_softmax()
{
    __shared__ float red[32];
    size_t row = blockIdx.x;
    float* p = g_logits + row * NN;
    int tid = threadIdx.x;
    int lane = tid & 31, wid = tid >> 5;
    float v0 = p[tid], v1 = p[tid + 256];
    float mv = fmaxf(v0, v1);
    #pragma unroll
    for (int o = 16; o > 0; o >>= 1) mv = fmaxf(mv, __shfl_xor_sync(0xffffffffu, mv, o));
    if (lane == 0) red[wid] = mv;
    __syncthreads();
    float mx = (lane < 8) ? red[lane] : -1e30f;
    #pragma unroll
    for (int o = 4; o > 0; o >>= 1) mx = fmaxf(mx, __shfl_xor_sync(0xffffffffu, mx, o));
    mx = __shfl_sync(0xffffffffu, mx, 0);
    if (wid == 0 && lane == 0) red[0] = mx;
    __syncthreads();
    mx = red[0];
    float e0 = __expf(v0 - mx), e1 = __expf(v1 - mx);
    float sv = e0 + e1;
    #pragma unroll
    for (int o = 16; o > 0; o >>= 1) sv += __shfl_xor_sync(0xffffffffu, sv, o);
    __syncthreads();
    if (lane == 0) red[wid] = sv;
    __syncthreads();
    float sm = (lane < 8) ? red[lane] : 0.f;
    #pragma unroll
    for (int o = 4; o > 0; o >>= 1) sm += __shfl_xor_sync(0xffffffffu, sm, o);
    if (wid == 0 && lane == 0) red[0] = sm;
    __syncthreads();
    float inv = 1.0f / red[0];
    p[tid] = e0 * inv;
    p[tid + 256] = e1 * inv;
}

// ================= K4: attention-weighted sums, tiled GEMM =================
// block = (b, h, itile of 64); out cols = 16 (v) + 24 (vg) = 40
__global__ void k4_attn()
{
    __shared__ float a_sh[64*68];    // [i][j] pad 68
    __shared__ float v_sh[64*41];    // [j][col] pad 41

    int blk = blockIdx.x;
    int it = blk & 7;
    int h  = (blk >> 3) % 12;
    int b  = blk / (8 * 12);
    int i0 = it * 64;
    int tid = threadIdx.x;

    int q  = tid & 7;        // 5 cols each
    int ip = tid >> 3;       // i in {ip, ip+32}
    float acc[2][5];
    #pragma unroll
    for (int u = 0; u < 2; u++)
        #pragma unroll
        for (int c = 0; c < 5; c++) acc[u][c] = 0.f;

    const float* Arow = g_logits + (((size_t)b * NH + h) * NN + i0) * NN;

    for (int jt = 0; jt < NN; jt += 64) {
        // load A tile [64 i][64 j]
        for (int idx = tid; idx < 64*64; idx += 256) {
            int ii = idx >> 6, jj = idx & 63;
            a_sh[ii*68 + jj] = Arow[(size_t)ii * NN + jt + jj];
        }
        // load V tile [64 j][40]
        for (int idx = tid; idx < 64*40; idx += 256) {
            int jj = idx / 40, c = idx - jj*40;
            int j = jt + jj;
            float v;
            if (c < 16) v = g_v [((size_t)b * NN + j) * HC   + h * NC + c];
            else        v = g_vg[((size_t)b * NN + j) * HPV3 + h * 24 + (c - 16)];
            v_sh[jj*41 + c] = v;
        }
        __syncthreads();
        #pragma unroll 4
        for (int jj = 0; jj < 64; jj++) {
            float a0 = a_sh[ip*68 + jj];
            float a1 = a_sh[(ip+32)*68 + jj];
            const float* vp = v_sh + jj*41 + q*5;
            #pragma unroll
            for (int c = 0; c < 5; c++) {
                float v = vp[c];
                acc[0][c] += a0 * v;
                acc[1][c] += a1 * v;
            }
        }
        __syncthreads();
    }

    #pragma unroll
    for (int u = 0; u < 2; u++) {
        int ig = i0 + ip + 32*u;
        #pragma unroll
        for (int c = 0; c < 5; c++) {
            int col = q*5 + c;
            if (col < 16) g_o  [((size_t)b * NN + ig) * HC   + h * NC + col]      = acc[u][c];
            else          g_opt[((size_t)b * NN + ig) * HPV3 + h * 24 + (col-16)] = acc[u][c];
        }
    }
}

// ================= K5: final features + output GEMV, 8 rows/block =================
#define K5R 8
__global__ void k5_out(const float* __restrict__ rot,
                       const float* __restrict__ trans,
                       const float* __restrict__ Wout,
                       const float* __restrict__ bout,
                       float* __restrict__ sout)
{
    __shared__ float feats[K5R*576];
    int bi0 = blockIdx.x * K5R;
    int tid = threadIdx.x;

    for (int idx = tid; idx < K5R*HC; idx += 384) {
        int r = idx / HC, c = idx - r*HC;
        feats[r*576 + c] = g_o[(size_t)(bi0+r) * HC + c];
    }
    for (int idx = tid; idx < K5R*96; idx += 384) {
        int r = idx / 96, kidx = idx - r*96;
        int bi = bi0 + r;
        const float* rp = rot + (size_t)bi * 9;
        const float* tp = trans + (size_t)bi * 3;
        float oy0 = g_opt[(size_t)bi * HPV3 + kidx*3+0] - tp[0] * 0.1f;
        float oy1 = g_opt[(size_t)bi * HPV3 + kidx*3+1] - tp[1] * 0.1f;
        float oy2 = g_opt[(size_t)bi * HPV3 + kidx*3+2] - tp[2] * 0.1f;
        float l0 = rp[0]*oy0 + rp[3]*oy1 + rp[6]*oy2;
        float l1 = rp[1]*oy0 + rp[4]*oy1 + rp[7]*oy2;
        float l2 = rp[2]*oy0 + rp[5]*oy1 + rp[8]*oy2;
        feats[r*576 + 192 + kidx] = l0;
        feats[r*576 + 288 + kidx] = l1;
        feats[r*576 + 384 + kidx] = l2;
        feats[r*576 + 480 + kidx] = sqrtf(l0*l0 + l1*l1 + l2*l2 + 1e-8f);
    }
    __syncthreads();

    int cs = tid;  // blockDim = 384
    float acc[K5R];
    float bb = bout[cs];
    #pragma unroll
    for (int r = 0; r < K5R; r++) acc[r] = bb;
    for (int f = 0; f < 576; f++) {
        float w = Wout[(size_t)f * CSD + cs];
        #pragma unroll
        for (int r = 0; r < K5R; r++) acc[r] += feats[r*576 + f] * w;
    }
    #pragma unroll
    for (int r = 0; r < K5R; r++)
        sout[(size_t)(bi0+r) * CSD + cs] = acc[r];
}

// ================= launch =================
extern "C" void kernel_launch(void* const* d_in, const int* in_sizes, int n_in,
                              void* d_out, int out_size)
{
    const float* s        = (const float*)d_in[0];
    const float* rot      = (const float*)d_in[1];
    const float* trans    = (const float*)d_in[2];
    const float* mask     = (const float*)d_in[3];
    const float* Wq       = (const float*)d_in[4];
    const float* bq       = (const float*)d_in[5];
    const float* Wkv      = (const float*)d_in[6];
    const float* bkv      = (const float*)d_in[7];
    const float* head_w   = (const float*)d_in[8];
    const float* ln_g     = (const float*)d_in[9];
    const float* ln_b     = (const float*)d_in[10];
    const float* Wpq      = (const float*)d_in[11];
    const float* bpq      = (const float*)d_in[12];
    const float* Wpv      = (const float*)d_in[13];
    const float* bpv      = (const float*)d_in[14];
    const float* Wvl      = (const float*)d_in[15];
    const float* gbf_mean = (const float*)d_in[16];
    const float* gbf_std  = (const float*)d_in[17];
    const float* Wg       = (const float*)d_in[18];
    const float* bg       = (const float*)d_in[19];
    const float* W1       = (const float*)d_in[20];
    const float* b1       = (const float*)d_in[21];
    const float* W2       = (const float*)d_in[22];
    const float* b2       = (const float*)d_in[23];
    const float* Wkvp     = (const float*)d_in[24];
    const float* bkvp     = (const float*)d_in[25];
    const float* Wout     = (const float*)d_in[26];
    const float* bout     = (const float*)d_in[27];

    float* out = (float*)d_out;
    float* sout_part = out;                              // (B,N,CS)
    float* g_part = out + (size_t)NB * NN * CSD;         // (B,N,N,G)

    cudaFuncSetAttribute((const void*)k2_pair,
                         cudaFuncAttributeMaxDynamicSharedMemorySize, SMEM2_BYTES);

    k1_project<<<NB * NN / K1R, 256>>>(s, rot, trans, Wq, bq, Wkv, bkv,
                                       ln_g, ln_b, Wpq, bpq, Wpv, bpv, Wkvp, bkvp);
    k2_pair<<<NB * NN, 256, SMEM2_BYTES>>>(rot, trans, mask, head_w, Wvl,
                                           gbf_mean, gbf_std, Wg, bg, W1, b1,
                                           W2, b2, g_part);
    k3_softmax<<<NB * NH * NN, 256>>>();
    k4_attn<<<NB * NH * (NN/64), 256>>>();
    k5_out<<<NB * NN / K5R, 384>>>(rot, trans, Wout, bout, sout_part);
}